// round 11
// baseline (speedup 1.0000x reference)
#include <cuda_runtime.h>
#include <cstdint>

// PolarToCartesianGrid: batched scatter-add into a cartesian voxel grid.
//
// R11: NO memset nodes, NO streams/events. Five same-stream kernels; each
// fuses "zero next slab-group with fire-and-forget float4 stores" with
// "scatter previous batch-group" in EVERY thread:
//   K0 : zero slabs 0-3  + pack idx[23b]|flags[6b] (hides under store drain)
//   K1 : zero slabs 4-7  + scatter batches 0-3
//   K2 : zero slabs 8-11 + scatter batches 4-7
//   K3 : zero slabs 12-15+ scatter batches 8-11
//   K4 :                   scatter batches 12-15
// zero(g) -> scatter(g) ordering comes from kernel boundaries; within a
// kernel the two roles touch DIFFERENT slabs. Stores are issued first and
// drain while the scatter's loads/shuffles/atomics execute.

#define NTHR 256
#define MAX_CELLS (1 << 21)
#define MAX_BATCHES 32
#define GROUP 4

__device__ unsigned g_packed[MAX_CELLS];   // idx[23b] | (flags[6b] << 23)

__global__ __launch_bounds__(NTHR)
void fused_kernel(const float* __restrict__ polar_g,  // batch group base (or null)
                  float*       __restrict__ out_g,    // slab group base  (or null)
                  float4*      __restrict__ zero_base,// slabs to zero    (or null)
                  long long zero_n4,
                  const int*   __restrict__ vidx,     // non-null in K0 only
                  int n_cells, long long n_vox, int nb)
{
    const int tid = blockIdx.x * blockDim.x + threadIdx.x;
    const unsigned FULL = 0xFFFFFFFFu;
    const int lane = threadIdx.x & 31;

    // ---- 1) zeroing: fire-and-forget coalesced float4 stores --------------
    if (zero_base) {
        const float4 z = make_float4(0.f, 0.f, 0.f, 0.f);
        const long long nthreads = (long long)gridDim.x * blockDim.x;
        for (long long i = tid; i < zero_n4; i += nthreads)
            zero_base[i] = z;
    }

    // ---- 2) pack (K0 only): idx + warp-segment flags into g_packed --------
    if (vidx && tid < n_cells) {
        const int idx = vidx[tid];
        const int prev = __shfl_up_sync(FULL, idx, 1);
        unsigned f = (lane == 0 || prev != idx) ? 1u : 0u;   // segment head
        int t;
        t = __shfl_down_sync(FULL, idx, 1);  if (lane + 1  < 32 && t == idx) f |= 2u;
        t = __shfl_down_sync(FULL, idx, 2);  if (lane + 2  < 32 && t == idx) f |= 4u;
        t = __shfl_down_sync(FULL, idx, 4);  if (lane + 4  < 32 && t == idx) f |= 8u;
        t = __shfl_down_sync(FULL, idx, 8);  if (lane + 8  < 32 && t == idx) f |= 16u;
        t = __shfl_down_sync(FULL, idx, 16); if (lane + 16 < 32 && t == idx) f |= 32u;
        g_packed[tid] = (unsigned)idx | (f << 23);           // n_vox < 2^23
    }

    // ---- 3) scatter nb batches: packed load + MLP loads + reductions ------
    if (nb > 0 && tid < n_cells) {
        const unsigned p   = g_packed[tid];
        const unsigned idx = p & 0x7FFFFFu;
        const unsigned f   = p >> 23;

        float v[GROUP];
        #pragma unroll
        for (int i = 0; i < GROUP; ++i)
            v[i] = (i < nb) ? __ldg(polar_g + (size_t)i * n_cells + tid) : 0.f;

        float t[GROUP];
        #pragma unroll
        for (int d = 1; d <= 16; d <<= 1) {
            #pragma unroll
            for (int i = 0; i < GROUP; ++i) t[i] = __shfl_down_sync(FULL, v[i], d);
            const unsigned bit = (unsigned)d << 1;           // d=1->2, ..., 16->32
            if (f & bit) {
                #pragma unroll
                for (int i = 0; i < GROUP; ++i) v[i] += t[i];
            }
        }

        if (f & 1u) {
            #pragma unroll
            for (int i = 0; i < GROUP; ++i)
                if (i < nb) atomicAdd(out_g + (long long)i * n_vox + idx, v[i]);
        }
    }
}

// fallback: R1-style serial path (no packing assumptions)
__global__ void scatter_fallback_kernel(const float* __restrict__ polar_b,
                                        const int*   __restrict__ vidx,
                                        float*       __restrict__ out_b,
                                        int n_cells)
{
    const int cell = blockIdx.x * blockDim.x + threadIdx.x;
    if (cell >= n_cells) return;
    const unsigned FULL = 0xFFFFFFFFu;
    const int lane = threadIdx.x & 31;
    const int idx = vidx[cell];
    float v = __ldg(polar_b + cell);
    const unsigned peers = __match_any_sync(FULL, idx);
    const int rank = __popc(peers & ((1u << lane) - 1u));
    const unsigned s1  = __fns(peers, lane, 2);
    const unsigned s2  = __fns(peers, lane, 3);
    const unsigned s4  = __fns(peers, lane, 5);
    const unsigned s8  = __fns(peers, lane, 9);
    const unsigned s16 = __fns(peers, lane, 17);
    float t;
    t = __shfl_sync(FULL, v, s1  & 31); if (s1  < 32) v += t;
    t = __shfl_sync(FULL, v, s2  & 31); if (s2  < 32) v += t;
    t = __shfl_sync(FULL, v, s4  & 31); if (s4  < 32) v += t;
    t = __shfl_sync(FULL, v, s8  & 31); if (s8  < 32) v += t;
    t = __shfl_sync(FULL, v, s16 & 31); if (s16 < 32) v += t;
    if (rank == 0) atomicAdd(out_b + idx, v);
}

extern "C" void kernel_launch(void* const* d_in, const int* in_sizes, int n_in,
                              void* d_out, int out_size)
{
    const float* polar = (const float*)d_in[0];            // [B,1,El,R,Az] f32
    const int*   vidx  = (const int*)d_in[1];              // [El*R*Az] int32
    float*       out   = (float*)d_out;                    // [B,1,Z,Y,X] f32

    const int n_cells = in_sizes[1];                       // 1,048,576
    int batches = in_sizes[0] / n_cells;                   // 16
    if (batches > MAX_BATCHES) batches = MAX_BATCHES;
    const long long n_vox = (long long)out_size / batches; // 8,192,000

    const int blocks = (n_cells + NTHR - 1) / NTHR;        // 4096
    const bool packable = (n_cells <= MAX_CELLS) &&
                          (n_vox < (1LL << 23)) && ((n_vox & 3LL) == 0);

    if (packable) {
        const int n_groups = (batches + GROUP - 1) / GROUP;    // 4
        // K0..K_{n_groups}: zero group k, scatter group k-1
        for (int k = 0; k <= n_groups; ++k) {
            const bool has_zero = (k < n_groups);
            const bool has_scat = (k > 0);

            const int zb0 = k * GROUP;
            const int znb = has_zero
                ? ((batches - zb0 < GROUP) ? (batches - zb0) : GROUP) : 0;
            float4* zbase = has_zero
                ? (float4*)(out + (long long)zb0 * n_vox) : nullptr;
            const long long zn4 = (long long)znb * (n_vox >> 2);

            const int sb0 = (k - 1) * GROUP;
            const int snb = has_scat
                ? ((batches - sb0 < GROUP) ? (batches - sb0) : GROUP) : 0;

            fused_kernel<<<blocks, NTHR>>>(
                has_scat ? polar + (size_t)sb0 * n_cells : nullptr,
                has_scat ? out + (long long)sb0 * n_vox  : nullptr,
                zbase, zn4,
                (k == 0) ? vidx : nullptr,
                n_cells, n_vox, snb);
        }
    } else {
        cudaMemsetAsync(d_out, 0, (size_t)out_size * sizeof(float), 0);
        for (int b = 0; b < batches; ++b)
            scatter_fallback_kernel<<<blocks, NTHR>>>(
                polar + (size_t)b * n_cells, vidx,
                out + (long long)b * n_vox, n_cells);
    }
}

// round 12
// speedup vs baseline: 1.0527x; 1.0527x over previous
#include <cuda_runtime.h>
#include <cstdint>

// PolarToCartesianGrid: batched scatter-add into a cartesian voxel grid.
//
// R12: serial engine memset (the only fast zeroing) + ONE scatter kernel for
// all 16 batches with per-block SMEM HASH dedup of atomic targets.
//   - pack kernel (idx[23b]|flags[6b]) runs concurrently with the memset
//     (fork/join, proven R9/R10).
//   - scatter: 256-thread block = 2 adjacent az-rows. Warp-segmented
//     reduction -> leaders insert voxel ids into a 512-entry smem hash ONCE
//     (keys are batch-invariant); per batch: leaders atomicAdd into smem
//     values, then the block flushes occupied entries with one global RED
//     each. Cross-warp az arcs and adjacent-r duplicates merge in smem,
//     cutting the global atomic count that dominated R1's 62us scatter.

#define NTHR 256
#define HN 512                 // smem hash slots (load factor <= 0.5)
#define MAX_CELLS (1 << 21)
#define MAX_BATCHES 32

__device__ unsigned g_packed[MAX_CELLS];   // idx[23b] | (flags[6b] << 23)

// flags: bit0 = segment head; bit{1..5} = lane+d (d=1,2,4,8,16) same index
__global__ void pack_kernel(const int* __restrict__ vidx, int n_cells)
{
    const int cell = blockIdx.x * blockDim.x + threadIdx.x;
    if (cell >= n_cells) return;
    const unsigned FULL = 0xFFFFFFFFu;
    const int lane = threadIdx.x & 31;

    const int idx = vidx[cell];
    const int prev = __shfl_up_sync(FULL, idx, 1);
    unsigned f = (lane == 0 || prev != idx) ? 1u : 0u;
    int t;
    t = __shfl_down_sync(FULL, idx, 1);  if (lane + 1  < 32 && t == idx) f |= 2u;
    t = __shfl_down_sync(FULL, idx, 2);  if (lane + 2  < 32 && t == idx) f |= 4u;
    t = __shfl_down_sync(FULL, idx, 4);  if (lane + 4  < 32 && t == idx) f |= 8u;
    t = __shfl_down_sync(FULL, idx, 8);  if (lane + 8  < 32 && t == idx) f |= 16u;
    t = __shfl_down_sync(FULL, idx, 16); if (lane + 16 < 32 && t == idx) f |= 32u;
    g_packed[cell] = (unsigned)idx | (f << 23);
}

__global__ __launch_bounds__(NTHR)
void scatter_hash_all(const float* __restrict__ polar,
                      float*       __restrict__ out,
                      int n_cells, int batches, long long n_vox)
{
    const unsigned FULL = 0xFFFFFFFFu;
    const int tid  = threadIdx.x;
    const int cell = blockIdx.x * NTHR + tid;
    const bool act = (cell < n_cells);

    __shared__ int   hkey[HN];
    __shared__ float hval[HN];

    // ---- build hash keys ONCE (batch-invariant leader/voxel structure) ----
    for (int i = tid; i < HN; i += NTHR) { hkey[i] = -1; hval[i] = 0.f; }
    __syncthreads();

    unsigned p = 0, f = 0; int idx = 0, slot = -1;
    if (act) {
        p   = g_packed[cell];
        idx = (int)(p & 0x7FFFFFu);
        f   = p >> 23;
        if (f & 1u) {
            unsigned h = ((unsigned)idx * 2654435761u >> 20) & (HN - 1);
            for (;;) {
                int old = atomicCAS(&hkey[h], -1, idx);
                if (old == -1 || old == idx) { slot = (int)h; break; }
                h = (h + 1) & (HN - 1);
            }
        }
    }
    __syncthreads();

    // ---- per batch: load, warp-reduce, smem-accumulate, flush -------------
    for (int b = 0; b < batches; ++b) {
        float v = 0.f;
        if (act) v = __ldg(polar + (size_t)b * n_cells + cell);

        float t;
        t = __shfl_down_sync(FULL, v, 1);  if (f & 2u)  v += t;
        t = __shfl_down_sync(FULL, v, 2);  if (f & 4u)  v += t;
        t = __shfl_down_sync(FULL, v, 4);  if (f & 8u)  v += t;
        t = __shfl_down_sync(FULL, v, 8);  if (f & 16u) v += t;
        t = __shfl_down_sync(FULL, v, 16); if (f & 32u) v += t;

        if (slot >= 0) atomicAdd(&hval[slot], v);
        __syncthreads();

        float* ob = out + (long long)b * n_vox;
        for (int i = tid; i < HN; i += NTHR) {
            const int k = hkey[i];
            if (k >= 0) {
                atomicAdd(ob + k, hval[i]);   // RED, no return
                hval[i] = 0.f;                // reset for next batch
            }
        }
        __syncthreads();
    }
}

// fallback: R1-style serial scatter (no packing assumptions)
__global__ void scatter_fallback_kernel(const float* __restrict__ polar_b,
                                        const int*   __restrict__ vidx,
                                        float*       __restrict__ out_b,
                                        int n_cells)
{
    const int cell = blockIdx.x * blockDim.x + threadIdx.x;
    if (cell >= n_cells) return;
    const unsigned FULL = 0xFFFFFFFFu;
    const int lane = threadIdx.x & 31;
    const int idx = vidx[cell];
    float v = __ldg(polar_b + cell);
    const unsigned peers = __match_any_sync(FULL, idx);
    const int rank = __popc(peers & ((1u << lane) - 1u));
    const unsigned s1  = __fns(peers, lane, 2);
    const unsigned s2  = __fns(peers, lane, 3);
    const unsigned s4  = __fns(peers, lane, 5);
    const unsigned s8  = __fns(peers, lane, 9);
    const unsigned s16 = __fns(peers, lane, 17);
    float t;
    t = __shfl_sync(FULL, v, s1  & 31); if (s1  < 32) v += t;
    t = __shfl_sync(FULL, v, s2  & 31); if (s2  < 32) v += t;
    t = __shfl_sync(FULL, v, s4  & 31); if (s4  < 32) v += t;
    t = __shfl_sync(FULL, v, s8  & 31); if (s8  < 32) v += t;
    t = __shfl_sync(FULL, v, s16 & 31); if (s16 < 32) v += t;
    if (rank == 0) atomicAdd(out_b + idx, v);
}

extern "C" void kernel_launch(void* const* d_in, const int* in_sizes, int n_in,
                              void* d_out, int out_size)
{
    const float* polar = (const float*)d_in[0];            // [B,1,El,R,Az] f32
    const int*   vidx  = (const int*)d_in[1];              // [El*R*Az] int32
    float*       out   = (float*)d_out;                    // [B,1,Z,Y,X] f32

    const int n_cells = in_sizes[1];                       // 1,048,576
    int batches = in_sizes[0] / n_cells;                   // 16
    if (batches > MAX_BATCHES) batches = MAX_BATCHES;
    const long long n_vox = (long long)out_size / batches; // 8,192,000

    const int blocks = (n_cells + NTHR - 1) / NTHR;        // 4096
    const bool packable = (n_cells <= MAX_CELLS) && (n_vox < (1LL << 23));

    cudaStream_t s2 = nullptr;
    cudaEvent_t  evZ = nullptr, evJoin = nullptr;
    bool multi = packable &&
                 (cudaStreamCreateWithFlags(&s2, cudaStreamNonBlocking) == cudaSuccess) &&
                 (cudaEventCreateWithFlags(&evZ, cudaEventDisableTiming) == cudaSuccess) &&
                 (cudaEventCreateWithFlags(&evJoin, cudaEventDisableTiming) == cudaSuccess);

    if (multi) {
        // stream 0: one full-size engine memset (fastest known zeroing)
        cudaMemsetAsync(d_out, 0, (size_t)out_size * sizeof(float), 0);
        cudaEventRecord(evZ, 0);
        // s2: pack overlaps the memset; scatter gated on the memset
        pack_kernel<<<blocks, NTHR, 0, s2>>>(vidx, n_cells);
        cudaStreamWaitEvent(s2, evZ, 0);
        scatter_hash_all<<<blocks, NTHR, 0, s2>>>(polar, out,
                                                  n_cells, batches, n_vox);
        cudaEventRecord(evJoin, s2);
        cudaStreamWaitEvent(0, evJoin, 0);
    } else {
        cudaMemsetAsync(d_out, 0, (size_t)out_size * sizeof(float), 0);
        for (int b = 0; b < batches; ++b)
            scatter_fallback_kernel<<<blocks, NTHR>>>(
                polar + (size_t)b * n_cells, vidx,
                out + (long long)b * n_vox, n_cells);
    }
}

// round 15
// speedup vs baseline: 1.1194x; 1.0634x over previous
#include <cuda_runtime.h>
#include <cstdint>

// PolarToCartesianGrid: batched scatter-add into a cartesian voxel grid.
//
// R15: SERIAL minimal-risk schedule (same shape as the R1 baseline that
// always runs) with the radial-quad scatter:
//   1) pack kernel (~2us): one uint4 of batch-invariant structure per quad
//   2) 524MB engine memset (fastest zeroing, 88us)
//   3) ONE quad-scatter kernel for all 16 batches (~40-48us predicted)
//
// Quad scatter: a thread owns 4 consecutive r-cells (same el,az). r-step
// 0.125m = half a voxel => ~2 cells/voxel radially everywhere (incl. far
// field where az-runs are singletons). The quad is exactly partitioned into
// prefix-run A / interior runs / suffix-run B; A and B are additionally
// az-aggregated across warp lanes with the 5-step segmented suffix
// reduction proven in R1-R12 (rel_err ~9e-7 every round).

#define NTHR 256
#define MAX_QUADS (1 << 19)
#define M23 0x7FFFFFu
#define SENT 0x7FFFFFu          // sentinel idx (n_vox < 2^23)

__device__ uint4 g_packed4[MAX_QUADS];

//  w.x = i0 | fA<<23   (fA: bit0 head, bits1-5 same@d=1,2,4,8,16 on A-idx)
//  w.y = i1 | m1e<<23 | mjoin<<24 | sA1<<25 | sA2<<26 | sA3<<27
//  w.z = i2 | m2e<<23 | sB1<<24  | sB2<<25
//  w.w = i3 | fB<<23  | alive<<29
__global__ void pack_quad_kernel(const int* __restrict__ vidx, int n_quads)
{
    const int q = blockIdx.x * blockDim.x + threadIdx.x;
    if (q >= n_quads) return;                   // n_quads % 256 == 0
    const unsigned FULL = 0xFFFFFFFFu;
    const int lane = threadIdx.x & 31;

    const int az   = q & 127;                   // Az = 128
    const int base = ((q >> 7) << 9) + az;      // rowquad*512 + az

    const int i0 = vidx[base];
    const int i1 = vidx[base + 128];
    const int i2 = vidx[base + 256];
    const int i3 = vidx[base + 384];

    const bool e1 = (i1 == i0), e2 = (i2 == i1), e3 = (i3 == i2);
    const bool sA1 = e1, sA2 = e1 && e2, sA3 = e1 && e2 && e3;
    const bool alive = !sA3;                    // B slot exists
    const bool sB2 = e3, sB1 = e3 && e2;

    const bool covB1 = sB1 && alive, covB2 = sB2 && alive;
    const bool m1 = !sA1 && !covB1;             // cell1 interior
    const bool m2 = !sA2 && !covB2;             // cell2 interior
    const bool mjoin = m1 && m2 && e2;          // cells 1,2 one interior run
    const bool m1e = m1;
    const bool m2e = m2 && !mjoin;

    // A-slot az flags (segmented suffix reduction over i0 across lanes)
    const int pA = __shfl_up_sync(FULL, i0, 1);
    unsigned fA = (lane == 0 || pA != i0) ? 1u : 0u;
    int t;
    t = __shfl_down_sync(FULL, i0, 1);  if (lane + 1  < 32 && t == i0) fA |= 2u;
    t = __shfl_down_sync(FULL, i0, 2);  if (lane + 2  < 32 && t == i0) fA |= 4u;
    t = __shfl_down_sync(FULL, i0, 4);  if (lane + 4  < 32 && t == i0) fA |= 8u;
    t = __shfl_down_sync(FULL, i0, 8);  if (lane + 8  < 32 && t == i0) fA |= 16u;
    t = __shfl_down_sync(FULL, i0, 16); if (lane + 16 < 32 && t == i0) fA |= 32u;

    // B-slot az flags on sentineled idx (dead lanes break runs, never emit)
    const int bidx = alive ? i3 : (int)SENT;
    const int pB = __shfl_up_sync(FULL, bidx, 1);
    unsigned fB = (alive && (lane == 0 || pB != bidx)) ? 1u : 0u;
    t = __shfl_down_sync(FULL, bidx, 1);  if (lane + 1  < 32 && t == bidx) fB |= 2u;
    t = __shfl_down_sync(FULL, bidx, 2);  if (lane + 2  < 32 && t == bidx) fB |= 4u;
    t = __shfl_down_sync(FULL, bidx, 4);  if (lane + 4  < 32 && t == bidx) fB |= 8u;
    t = __shfl_down_sync(FULL, bidx, 8);  if (lane + 8  < 32 && t == bidx) fB |= 16u;
    t = __shfl_down_sync(FULL, bidx, 16); if (lane + 16 < 32 && t == bidx) fB |= 32u;

    uint4 w;
    w.x = (unsigned)i0 | (fA << 23);
    w.y = (unsigned)i1 | ((unsigned)m1e << 23) | ((unsigned)mjoin << 24)
        | ((unsigned)sA1 << 25) | ((unsigned)sA2 << 26) | ((unsigned)sA3 << 27);
    w.z = (unsigned)i2 | ((unsigned)m2e << 23)
        | ((unsigned)sB1 << 24) | ((unsigned)sB2 << 25);
    w.w = (unsigned)i3 | (fB << 23) | ((unsigned)alive << 29);
    g_packed4[q] = w;
}

__global__ __launch_bounds__(NTHR)
void scatter_quad_kernel(const float* __restrict__ polar,
                         float*       __restrict__ out,
                         int n_cells, int batches, long long n_vox, int n_quads)
{
    const int q = blockIdx.x * blockDim.x + threadIdx.x;
    if (q >= n_quads) return;
    const unsigned FULL = 0xFFFFFFFFu;

    const int az   = q & 127;
    const int base = ((q >> 7) << 9) + az;

    const uint4 w = g_packed4[q];
    const unsigned i0 = w.x & M23, fA = (w.x >> 23) & 63u;
    const unsigned i1 = w.y & M23;
    const bool  m1e   = (w.y >> 23) & 1u;
    const float mj    = ((w.y >> 24) & 1u) ? 1.f : 0.f;
    const float mA1   = ((w.y >> 25) & 1u) ? 1.f : 0.f;
    const float mA2   = ((w.y >> 26) & 1u) ? 1.f : 0.f;
    const float mA3   = ((w.y >> 27) & 1u) ? 1.f : 0.f;
    const unsigned i2 = w.z & M23;
    const bool  m2e   = (w.z >> 23) & 1u;
    const float mB1   = ((w.z >> 24) & 1u) ? 1.f : 0.f;
    const float mB2   = ((w.z >> 25) & 1u) ? 1.f : 0.f;
    const unsigned i3 = w.w & M23, fB = (w.w >> 23) & 63u;
    const float mAl   = ((w.w >> 29) & 1u) ? 1.f : 0.f;

    for (int b = 0; b < batches; ++b) {
        const float* p = polar + (size_t)b * n_cells + base;
        const float v0 = __ldg(p);
        const float v1 = __ldg(p + 128);
        const float v2 = __ldg(p + 256);
        const float v3 = __ldg(p + 384);

        float vA = v0 + mA1 * v1 + mA2 * v2 + mA3 * v3;   // prefix run
        float vB = mAl * (v3 + mB2 * v2 + mB1 * v1);      // suffix run (0 if dead)
        const float mv1 = v1 + mj * v2;                   // interior run at i1

        // interleaved A/B az-segmented suffix reductions
        float tA, tB;
        tA = __shfl_down_sync(FULL, vA, 1);  tB = __shfl_down_sync(FULL, vB, 1);
        if (fA & 2u)  vA += tA;              if (fB & 2u)  vB += tB;
        tA = __shfl_down_sync(FULL, vA, 2);  tB = __shfl_down_sync(FULL, vB, 2);
        if (fA & 4u)  vA += tA;              if (fB & 4u)  vB += tB;
        tA = __shfl_down_sync(FULL, vA, 4);  tB = __shfl_down_sync(FULL, vB, 4);
        if (fA & 8u)  vA += tA;              if (fB & 8u)  vB += tB;
        tA = __shfl_down_sync(FULL, vA, 8);  tB = __shfl_down_sync(FULL, vB, 8);
        if (fA & 16u) vA += tA;              if (fB & 16u) vB += tB;
        tA = __shfl_down_sync(FULL, vA, 16); tB = __shfl_down_sync(FULL, vB, 16);
        if (fA & 32u) vA += tA;              if (fB & 32u) vB += tB;

        float* ob = out + (long long)b * n_vox;
        if (fA & 1u) atomicAdd(ob + i0, vA);
        if (fB & 1u) atomicAdd(ob + i3, vB);
        if (m1e)     atomicAdd(ob + i1, mv1);
        if (m2e)     atomicAdd(ob + i2, v2);
    }
}

// fallback: R1-style serial scatter (no layout assumptions)
__global__ void scatter_fallback_kernel(const float* __restrict__ polar_b,
                                        const int*   __restrict__ vidx,
                                        float*       __restrict__ out_b,
                                        int n_cells)
{
    const int cell = blockIdx.x * blockDim.x + threadIdx.x;
    if (cell >= n_cells) return;
    const unsigned FULL = 0xFFFFFFFFu;
    const int lane = threadIdx.x & 31;
    const int idx = vidx[cell];
    float v = __ldg(polar_b + cell);
    const unsigned peers = __match_any_sync(FULL, idx);
    const int rank = __popc(peers & ((1u << lane) - 1u));
    const unsigned s1  = __fns(peers, lane, 2);
    const unsigned s2  = __fns(peers, lane, 3);
    const unsigned s4  = __fns(peers, lane, 5);
    const unsigned s8  = __fns(peers, lane, 9);
    const unsigned s16 = __fns(peers, lane, 17);
    float t;
    t = __shfl_sync(FULL, v, s1  & 31); if (s1  < 32) v += t;
    t = __shfl_sync(FULL, v, s2  & 31); if (s2  < 32) v += t;
    t = __shfl_sync(FULL, v, s4  & 31); if (s4  < 32) v += t;
    t = __shfl_sync(FULL, v, s8  & 31); if (s8  < 32) v += t;
    t = __shfl_sync(FULL, v, s16 & 31); if (s16 < 32) v += t;
    if (rank == 0) atomicAdd(out_b + idx, v);
}

extern "C" void kernel_launch(void* const* d_in, const int* in_sizes, int n_in,
                              void* d_out, int out_size)
{
    const float* polar = (const float*)d_in[0];            // [B,1,32,256,128] f32
    const int*   vidx  = (const int*)d_in[1];              // [1048576] int32
    float*       out   = (float*)d_out;                    // [B,1,80,320,320] f32

    const int n_cells = in_sizes[1];
    const int batches = in_sizes[0] / n_cells;             // 16
    const long long n_vox = (long long)out_size / batches; // 8,192,000

    // quad layout assumes El*R*Az with Az=128, R%4==0 (fixed for this problem)
    const bool quadable = (n_cells == (1 << 20)) && (n_vox < (1LL << 23));

    if (quadable) {
        const int n_quads = n_cells / 4;                   // 262144
        const int qblocks = n_quads / NTHR;                // 1024

        pack_quad_kernel<<<qblocks, NTHR>>>(vidx, n_quads);
        cudaMemsetAsync(d_out, 0, (size_t)out_size * sizeof(float), 0);
        scatter_quad_kernel<<<qblocks, NTHR>>>(polar, out,
                                               n_cells, batches, n_vox, n_quads);
    } else {
        cudaMemsetAsync(d_out, 0, (size_t)out_size * sizeof(float), 0);
        const int blocks = (n_cells + NTHR - 1) / NTHR;
        for (int b = 0; b < batches; ++b)
            scatter_fallback_kernel<<<blocks, NTHR>>>(
                polar + (size_t)b * n_cells, vidx,
                out + (long long)b * n_vox, n_cells);
    }
}